// round 13
// baseline (speedup 1.0000x reference)
#include <cuda_runtime.h>
#include <math.h>

// HyperbolicMLR fused scalar kernel, smem/fma co-balanced at 1 B/MAC.
// f32x2 pair = (p,a): one FFMA2 feeds both GEMMs. Thread tile 8b x 4c.
// Block: 64 threads, 64 batch x 32 classes. Grid 32x32 = 1024 blocks, 6/SM.

#define K_CURV 0.1f
#define SQRT_K 0.31622776601683794f

typedef unsigned long long ull;

__device__ __forceinline__ ull pack2(float a, float b) {
    ull r;
    asm("mov.b64 %0, {%1, %2};" : "=l"(r) : "f"(a), "f"(b));
    return r;
}
__device__ __forceinline__ float2 unpack2(ull v) {
    float2 r;
    asm("mov.b64 {%0, %1}, %2;" : "=f"(r.x), "=f"(r.y) : "l"(v));
    return r;
}
__device__ __forceinline__ void ffma2(ull& acc, ull a, ull b) {
    asm("fma.rn.f32x2 %0, %1, %2, %0;" : "+l"(acc) : "l"(a), "l"(b));
}
__device__ __forceinline__ float rcp_a(float x)  { float r; asm("rcp.approx.f32 %0, %1;"  : "=f"(r) : "f"(x)); return r; }
__device__ __forceinline__ float sqrt_a(float x) { float r; asm("sqrt.approx.f32 %0, %1;" : "=f"(r) : "f"(x)); return r; }
__device__ __forceinline__ float lg2_a(float x)  { float r; asm("lg2.approx.f32 %0, %1;"  : "=f"(r) : "f"(x)); return r; }

__global__ void __launch_bounds__(64, 6)
hmlr_fused(const float* __restrict__ x,
           const float* __restrict__ a_vals,
           const float* __restrict__ p_vals,
           float* __restrict__ out, int B, int C) {
    __shared__ __align__(16) float xs[64 * 64];   // [d][b], plain (conflict-free)
    __shared__ __align__(16) float pa[64 * 64];   // [d][granules (p,a,p',a') x8 | x8]
    __shared__ float s_x2[32], s_pc[32], s_sc[32], s_cf[32], s_y2[64];

    const int tid   = threadIdx.x;
    const int cBase = blockIdx.x * 32;
    const int bBase = blockIdx.y * 64;

    // ===== phase 1a: x fill (transpose to [d][b]) + y2; thread = one b row =====
    {
        const float4* xr = (const float4*)(x + (size_t)(bBase + tid) * 64);
        float s = 0.f;
#pragma unroll
        for (int i = 0; i < 16; ++i) {
            float4 v = xr[i];
            s += v.x * v.x + v.y * v.y + v.z * v.z + v.w * v.w;
            xs[(4 * i + 0) * 64 + tid] = v.x;   // lanes = consecutive b -> 32 banks
            xs[(4 * i + 1) * 64 + tid] = v.y;
            xs[(4 * i + 2) * 64 + tid] = v.z;
            xs[(4 * i + 3) * 64 + tid] = v.w;
        }
        s_y2[tid] = s;
    }

    // ===== phase 1b: class prep; 2 threads per class (d halves of 32) ==========
    {
        const int cl = tid >> 1;                 // local class 0..31
        const int sq = tid & 1;                  // d in [sq*32, sq*32+32)
        const int cc = cBase + cl;
        const bool valid = (cc < C);

        float P[32], A[32];
        if (valid) {
            const float4* pb4 = (const float4*)(p_vals + (size_t)cc * 64 + sq * 32);
            const float4* ab4 = (const float4*)(a_vals + (size_t)cc * 64 + sq * 32);
#pragma unroll
            for (int i = 0; i < 8; ++i) {
                float4 pv = pb4[i], av = ab4[i];
                P[4*i+0]=pv.x; P[4*i+1]=pv.y; P[4*i+2]=pv.z; P[4*i+3]=pv.w;
                A[4*i+0]=av.x; A[4*i+1]=av.y; A[4*i+2]=av.z; A[4*i+3]=av.w;
            }
        } else {
#pragma unroll
            for (int i = 0; i < 32; ++i) { P[i] = 0.f; A[i] = 0.f; }
        }

        float psq = 0.f;
#pragma unroll
        for (int i = 0; i < 32; ++i) psq += P[i] * P[i];
        psq += __shfl_xor_sync(0xffffffffu, psq, 1);

        float pn  = fmaxf(sqrtf(psq), 1e-15f);
        float arg = SQRT_K * pn;
        float t   = tanhf(arg) / arg;            // exp0 factor
        float p2  = t * t * psq;                 // |p_poin|^2
        float fac = 1.f + K_CURV * p2;

        float a2 = 0.f, pad = 0.f;
#pragma unroll
        for (int i = 0; i < 32; ++i) {
            float pp = t * P[i];
            float ap = fac * A[i];
            P[i] = pp; A[i] = ap;
            a2  += ap * ap;
            pad += pp * ap;
        }
        a2  += __shfl_xor_sync(0xffffffffu, a2, 1);
        pad += __shfl_xor_sync(0xffffffffu, pad, 1);

        if (sq == 0) {
            float an  = fmaxf(sqrtf(a2), 1e-15f);
            float lam = 2.f / (1.f - K_CURV * p2);
            s_x2[cl] = p2;
            s_pc[cl] = -pad;                     // dot(mp, a_poin)
            s_sc[cl] = lam * an / SQRT_K;        // scale
            s_cf[cl] = 2.f * SQRT_K / an;        // folded consts
        }
        // granule layout per d-row (64 floats):
        //   floats [tx*4 .. +3]      = (p[4tx], a[4tx], p[4tx+1], a[4tx+1])
        //   floats [32 + tx*4 .. +3] = (p[4tx+2], a[4tx+2], p[4tx+3], a[4tx+3])
        const int off = ((cl & 2) << 4) + ((cl >> 2) << 2) + ((cl & 1) << 1);
#pragma unroll
        for (int i = 0; i < 32; ++i) {
            int d = sq * 32 + i;
            *(float2*)(pa + d * 64 + off) = make_float2(P[i], A[i]);
        }
    }
    __syncthreads();

    // ===== phase 2: dual GEMM, 8b x 4c, 1 B/MAC =================================
    const int tx = tid & 7;                      // classes 4*tx .. 4*tx+3
    const int ty = tid >> 3;                     // b rows  8*ty .. 8*ty+7
    const float* xrow = xs + ty * 8;
    const float* crow = pa + tx * 4;

    ull acc[8][4];                               // [i=b][j=c] = (dotp, dota)
#pragma unroll
    for (int i = 0; i < 8; ++i)
#pragma unroll
        for (int j = 0; j < 4; ++j) acc[i][j] = 0ull;

#pragma unroll 8
    for (int d = 0; d < 64; ++d) {
        const float4 xv0 = *(const float4*)(xrow + d * 64);        // b0..b3
        const float4 xv1 = *(const float4*)(xrow + d * 64 + 4);    // b4..b7
        const ulonglong2 cA = *(const ulonglong2*)(crow + d * 64);       // (p0,a0),(p1,a1)
        const ulonglong2 cB = *(const ulonglong2*)(crow + d * 64 + 32);  // (p2,a2),(p3,a3)
        ull xb[8];
        xb[0] = pack2(xv0.x, xv0.x); xb[1] = pack2(xv0.y, xv0.y);
        xb[2] = pack2(xv0.z, xv0.z); xb[3] = pack2(xv0.w, xv0.w);
        xb[4] = pack2(xv1.x, xv1.x); xb[5] = pack2(xv1.y, xv1.y);
        xb[6] = pack2(xv1.z, xv1.z); xb[7] = pack2(xv1.w, xv1.w);
#pragma unroll
        for (int i = 0; i < 8; ++i) {
            ffma2(acc[i][0], xb[i], cA.x);
            ffma2(acc[i][1], xb[i], cA.y);
            ffma2(acc[i][2], xb[i], cB.x);
            ffma2(acc[i][3], xb[i], cB.y);
        }
    }

    // ===== phase 3: epilogue ====================================================
    const int cg = cBase + tx * 4;
    const bool wr = (cg + 3) < C;                // all-in or all-out per float4
    float x2a[4], pca[4], sca[4], cfa[4];
#pragma unroll
    for (int j = 0; j < 4; ++j) {
        x2a[j] = s_x2[tx * 4 + j];
        pca[j] = s_pc[tx * 4 + j];
        sca[j] = s_sc[tx * 4 + j];
        cfa[j] = s_cf[tx * 4 + j];
    }

#pragma unroll
    for (int i = 0; i < 8; ++i) {
        const float y2 = s_y2[ty * 8 + i];
        float4 r;
        float* rp = (float*)&r;
#pragma unroll
        for (int j = 0; j < 4; ++j) {
            float2 d2 = unpack2(acc[i][j]);      // (dot(p,x), dot(a,x))
            float x2  = x2a[j];
            float xy  = -d2.x;                   // dot(mp, x)
            float Bf  = 1.f - K_CURV * x2;
            float base = fmaf(2.f * K_CURV, xy, 1.f);
            float Af   = fmaf(K_CURV, y2, base);
            float den  = fmaf((K_CURV * K_CURV) * x2, y2, base);
            float dotnum = fmaf(Af, pca[j], Bf * d2.y);
            float num  = fmaf(Af, fmaf(Af, x2, 2.f * Bf * xy), Bf * Bf * y2);
            float w    = fmaf(den, den, -K_CURV * num);
            float ratio = cfa[j] * dotnum * den * rcp_a(w);
            float tt = fabsf(ratio);
            float z  = lg2_a(tt + sqrt_a(fmaf(tt, tt, 1.f))) * 0.69314718056f;
            rp[j] = sca[j] * copysignf(z, ratio);
        }
        if (wr) {
            const int bg = bBase + ty * 8 + i;
            *(float4*)(out + (size_t)bg * C + cg) = r;
        }
    }
}

// ===================== launch ==================================================
extern "C" void kernel_launch(void* const* d_in, const int* in_sizes, int n_in,
                              void* d_out, int out_size) {
    const float* x = (const float*)d_in[0];
    const float* a = (const float*)d_in[1];
    const float* p = (const float*)d_in[2];
    float* out = (float*)d_out;
    const int B = in_sizes[0] / 64;   // 2048
    const int C = in_sizes[1] / 64;   // 1000

    dim3 grid((C + 31) / 32, B / 64); // 32 x 32 = 1024 blocks, 64 thr, 6/SM
    hmlr_fused<<<grid, 64>>>(x, a, p, out, B, C);
}

// round 14
// speedup vs baseline: 1.7028x; 1.7028x over previous
#include <cuda_runtime.h>
#include <cuda_bf16.h>
#include <math.h>

// HyperbolicMLR via HMMA (mma.sync m16n8k16 bf16, fp32 acc) with hi/lo error split.
// B tile rows interleaved (n=2c -> p_poin, n=2c+1 -> a_poin): accumulator pairs
// come out as (dotp, dota) per class. CTA: 128 batch x 64 classes, 8 warps.

#define K_CURV 0.1f
#define SQRT_K 0.31622776601683794f

typedef unsigned int u32;

#define LDB   144                     // padded row stride in bytes (72 halves)
#define SB_AH 0                       // A hi: 128 rows x 144B
#define SB_AL (SB_AH + 128*LDB)
#define SB_BH (SB_AL + 128*LDB)      // B hi: 128 rows (2c=p, 2c+1=a)
#define SB_BL (SB_BH + 128*LDB)
#define SB_X2 (SB_BL + 128*LDB)      // |p_poin|^2      [64] f32
#define SB_PC (SB_X2 + 256)          // dot(mp,a_poin)  [64]
#define SB_SC (SB_PC + 256)          // scale           [64]
#define SB_CF (SB_SC + 256)          // 2*sqrt_k/a_norm [64]
#define SB_Y2 (SB_CF + 256)          // |x_b|^2         [128]
#define SB_TOTAL (SB_Y2 + 512)

static __device__ __forceinline__ u32 smem_u32(const void* p) {
    u32 a;
    asm("{ .reg .u64 t; cvta.to.shared.u64 t, %1; cvt.u32.u64 %0, t; }" : "=r"(a) : "l"(p));
    return a;
}
static __device__ __forceinline__ void ldm_x4(u32* r, u32 addr) {
    asm volatile("ldmatrix.sync.aligned.m8n8.x4.shared.b16 {%0,%1,%2,%3}, [%4];"
                 : "=r"(r[0]), "=r"(r[1]), "=r"(r[2]), "=r"(r[3]) : "r"(addr));
}
static __device__ __forceinline__ void ldm_x2(u32* r, u32 addr) {
    asm volatile("ldmatrix.sync.aligned.m8n8.x2.shared.b16 {%0,%1}, [%2];"
                 : "=r"(r[0]), "=r"(r[1]) : "r"(addr));
}
static __device__ __forceinline__ void mma16816(float* c, const u32* a, const u32* b) {
    asm volatile("mma.sync.aligned.m16n8k16.row.col.f32.bf16.bf16.f32 "
                 "{%0,%1,%2,%3}, {%4,%5,%6,%7}, {%8,%9}, {%0,%1,%2,%3};"
                 : "+f"(c[0]), "+f"(c[1]), "+f"(c[2]), "+f"(c[3])
                 : "r"(a[0]), "r"(a[1]), "r"(a[2]), "r"(a[3]), "r"(b[0]), "r"(b[1]));
}
static __device__ __forceinline__ float rcp_a(float x)  { float r; asm("rcp.approx.f32 %0, %1;"  : "=f"(r) : "f"(x)); return r; }
static __device__ __forceinline__ float sqrt_a(float x) { float r; asm("sqrt.approx.f32 %0, %1;" : "=f"(r) : "f"(x)); return r; }
static __device__ __forceinline__ float lg2_a(float x)  { float r; asm("lg2.approx.f32 %0, %1;"  : "=f"(r) : "f"(x)); return r; }

static __device__ __forceinline__ u32 hilo_hi2(float a, float b,
                                               float& ra, float& rb) {
    __nv_bfloat16 ha = __float2bfloat16_rn(a);
    __nv_bfloat16 hb = __float2bfloat16_rn(b);
    ra = a - __bfloat162float(ha);
    rb = b - __bfloat162float(hb);
    return (u32)__bfloat16_as_ushort(ha) | ((u32)__bfloat16_as_ushort(hb) << 16);
}
static __device__ __forceinline__ u32 bf2(float a, float b) {
    return (u32)__bfloat16_as_ushort(__float2bfloat16_rn(a))
         | ((u32)__bfloat16_as_ushort(__float2bfloat16_rn(b)) << 16);
}

__global__ void __launch_bounds__(256)
hmlr_hmma(const float* __restrict__ x,
          const float* __restrict__ a_vals,
          const float* __restrict__ p_vals,
          float* __restrict__ out, int B, int C) {
    extern __shared__ __align__(16) char sm[];
    float* s_x2 = (float*)(sm + SB_X2);
    float* s_pc = (float*)(sm + SB_PC);
    float* s_sc = (float*)(sm + SB_SC);
    float* s_cf = (float*)(sm + SB_CF);
    float* s_y2 = (float*)(sm + SB_Y2);
    const u32 sb = smem_u32(sm);

    const int tid   = threadIdx.x;
    const int lane  = tid & 31;
    const int w     = tid >> 5;
    const int cBase = blockIdx.x * 64;
    const int bBase = blockIdx.y * 128;

    // ===== phase 1a: x rows -> A hi/lo (bf16) + y2. 2 threads per row. ========
    {
        const int r = tid >> 1;
        const int h = tid & 1;                  // k half: 0..31 / 32..63
        const float4* xr = (const float4*)(x + (size_t)(bBase + r) * 64 + h * 32);
        float v[32]; float s = 0.f;
#pragma unroll
        for (int i = 0; i < 8; ++i) {
            float4 q = xr[i];
            v[4*i+0]=q.x; v[4*i+1]=q.y; v[4*i+2]=q.z; v[4*i+3]=q.w;
            s += q.x*q.x + q.y*q.y + q.z*q.z + q.w*q.w;
        }
        s += __shfl_xor_sync(0xffffffffu, s, 1);
        if (h == 0) s_y2[r] = s;
        char* rowH = sm + SB_AH + r * LDB + h * 64;
        char* rowL = sm + SB_AL + r * LDB + h * 64;
#pragma unroll
        for (int i = 0; i < 16; ++i) {
            float la, lb;
            u32 hh = hilo_hi2(v[2*i], v[2*i+1], la, lb);
            *(u32*)(rowH + 4*i) = hh;
            *(u32*)(rowL + 4*i) = bf2(la, lb);
        }
    }

    // ===== phase 1b: class prep -> B rows 2c (p), 2c+1 (a), hi/lo =============
    {
        const int cl = tid >> 2;                // local class 0..63
        const int sq = tid & 3;                 // d in [sq*16, +16)
        const int cc = cBase + cl;
        const bool valid = (cc < C);

        float P[16], A[16];
        if (valid) {
            const float4* pb4 = (const float4*)(p_vals + (size_t)cc * 64 + sq * 16);
            const float4* ab4 = (const float4*)(a_vals + (size_t)cc * 64 + sq * 16);
#pragma unroll
            for (int i = 0; i < 4; ++i) {
                float4 pv = pb4[i], av = ab4[i];
                P[4*i+0]=pv.x; P[4*i+1]=pv.y; P[4*i+2]=pv.z; P[4*i+3]=pv.w;
                A[4*i+0]=av.x; A[4*i+1]=av.y; A[4*i+2]=av.z; A[4*i+3]=av.w;
            }
        } else {
#pragma unroll
            for (int i = 0; i < 16; ++i) { P[i] = 0.f; A[i] = 0.f; }
        }

        float psq = 0.f;
#pragma unroll
        for (int i = 0; i < 16; ++i) psq += P[i] * P[i];
        psq += __shfl_xor_sync(0xffffffffu, psq, 1);
        psq += __shfl_xor_sync(0xffffffffu, psq, 2);

        float pn  = fmaxf(sqrtf(psq), 1e-15f);
        float arg = SQRT_K * pn;
        float t   = tanhf(arg) / arg;           // exp0 factor
        float p2  = t * t * psq;                // |p_poin|^2
        float fac = 1.f + K_CURV * p2;

        float a2 = 0.f, pad = 0.f;
#pragma unroll
        for (int i = 0; i < 16; ++i) {
            float pp = t * P[i];
            float ap = fac * A[i];
            P[i] = pp; A[i] = ap;
            a2  += ap * ap;
            pad += pp * ap;
        }
        a2  += __shfl_xor_sync(0xffffffffu, a2, 1);
        a2  += __shfl_xor_sync(0xffffffffu, a2, 2);
        pad += __shfl_xor_sync(0xffffffffu, pad, 1);
        pad += __shfl_xor_sync(0xffffffffu, pad, 2);

        if (sq == 0) {
            float an  = fmaxf(sqrtf(a2), 1e-15f);
            float lam = 2.f / (1.f - K_CURV * p2);
            s_x2[cl] = p2;
            s_pc[cl] = -pad;                    // dot(mp, a_poin)
            s_sc[cl] = lam * an / SQRT_K;       // scale
            s_cf[cl] = 2.f * SQRT_K / an;       // folded consts
        }
        char* pH = sm + SB_BH + (2*cl)   * LDB + sq * 32;
        char* pL = sm + SB_BL + (2*cl)   * LDB + sq * 32;
        char* aH = sm + SB_BH + (2*cl+1) * LDB + sq * 32;
        char* aL = sm + SB_BL + (2*cl+1) * LDB + sq * 32;
#pragma unroll
        for (int i = 0; i < 8; ++i) {
            float la, lb;
            u32 hh = hilo_hi2(P[2*i], P[2*i+1], la, lb);
            *(u32*)(pH + 4*i) = hh;
            *(u32*)(pL + 4*i) = bf2(la, lb);
            hh = hilo_hi2(A[2*i], A[2*i+1], la, lb);
            *(u32*)(aH + 4*i) = hh;
            *(u32*)(aL + 4*i) = bf2(la, lb);
        }
    }
    __syncthreads();

    // ===== phase 2: HMMA mainloop. Warp tile 32m x 64n, K=64 ===================
    const int m0 = (w & 3) * 32;
    const int n0 = (w >> 2) * 64;
    const int l16 = lane & 15;

    // A ldmatrix lane address bytes (per m-atom), k advances by +32B per step
    const u32 aoff0 = (u32)((m0      + l16) * LDB + (lane >> 4) * 16);
    const u32 aoff1 = (u32)((m0 + 16 + l16) * LDB + (lane >> 4) * 16);
    // B ldmatrix (x2) lane address bytes (n-atom 0), +1152B per n-atom
    const u32 boff  = (u32)((n0 + (l16 & 7)) * LDB + ((l16 >> 3) & 1) * 16);

    float acc[2][8][4];
#pragma unroll
    for (int ma = 0; ma < 2; ++ma)
#pragma unroll
        for (int nb = 0; nb < 8; ++nb)
#pragma unroll
            for (int q = 0; q < 4; ++q) acc[ma][nb][q] = 0.f;

#pragma unroll
    for (int kk = 0; kk < 4; ++kk) {
        const u32 kb = kk * 32;
        u32 ah0[4], ah1[4], al0[4], al1[4];
        ldm_x4(ah0, sb + SB_AH + aoff0 + kb);
        ldm_x4(ah1, sb + SB_AH + aoff1 + kb);
        ldm_x4(al0, sb + SB_AL + aoff0 + kb);
        ldm_x4(al1, sb + SB_AL + aoff1 + kb);
#pragma unroll
        for (int nb = 0; nb < 8; ++nb) {
            u32 bh[2], bl[2];
            ldm_x2(bh, sb + SB_BH + boff + nb * (8 * LDB) + kb);
            ldm_x2(bl, sb + SB_BL + boff + nb * (8 * LDB) + kb);
            mma16816(acc[0][nb], ah0, bh);
            mma16816(acc[1][nb], ah1, bh);
            mma16816(acc[0][nb], al0, bh);
            mma16816(acc[1][nb], al1, bh);
            mma16816(acc[0][nb], ah0, bl);
            mma16816(acc[1][nb], ah1, bl);
        }
    }

    // ===== phase 3: epilogue (register-local (dotp,dota) pairs) ================
    const int tg  = lane & 3;
    const int gid = lane >> 2;
#pragma unroll
    for (int nb = 0; nb < 8; ++nb) {
        const int cl = (n0 >> 1) + nb * 4 + tg;  // local class 0..63
        const int cg = cBase + cl;
        const float x2c = s_x2[cl];
        const float pcc = s_pc[cl];
        const float scc = s_sc[cl];
        const float cfc = s_cf[cl];
        const float Bf  = 1.f - K_CURV * x2c;
#pragma unroll
        for (int ma = 0; ma < 2; ++ma) {
#pragma unroll
            for (int h = 0; h < 2; ++h) {
                const int m  = m0 + ma * 16 + gid + h * 8;
                const float y2 = s_y2[m];
                const float dotp = acc[ma][nb][2*h];
                const float dota = acc[ma][nb][2*h+1];
                float xy   = -dotp;
                float base = fmaf(2.f * K_CURV, xy, 1.f);
                float Af   = fmaf(K_CURV, y2, base);
                float den  = fmaf((K_CURV * K_CURV) * x2c, y2, base);
                float dotnum = fmaf(Af, pcc, Bf * dota);
                float num  = fmaf(Af, fmaf(Af, x2c, 2.f * Bf * xy), Bf * Bf * y2);
                float wv   = fmaf(den, den, -K_CURV * num);
                float ratio = cfc * dotnum * den * rcp_a(wv);
                float tt = fabsf(ratio);
                float z  = lg2_a(tt + sqrt_a(fmaf(tt, tt, 1.f))) * 0.69314718056f;
                float rv = scc * copysignf(z, ratio);
                if (cg < C) out[(size_t)(bBase + m) * C + cg] = rv;
            }
        }
    }
}

// ===================== launch ==================================================
extern "C" void kernel_launch(void* const* d_in, const int* in_sizes, int n_in,
                              void* d_out, int out_size) {
    const float* x = (const float*)d_in[0];
    const float* a = (const float*)d_in[1];
    const float* p = (const float*)d_in[2];
    float* out = (float*)d_out;
    const int B = in_sizes[0] / 64;   // 2048
    const int C = in_sizes[1] / 64;   // 1000

    cudaFuncSetAttribute(hmlr_hmma, cudaFuncAttributeMaxDynamicSharedMemorySize, SB_TOTAL);
    dim3 grid((C + 63) / 64, B / 128);   // 16 x 16 = 256 CTAs, 2/SM, single wave
    hmlr_hmma<<<grid, 256, SB_TOTAL>>>(x, a, p, out, B, C);
}